// round 1
// baseline (speedup 1.0000x reference)
#include <cuda_runtime.h>
#include <cuda_bf16.h>
#include <math.h>

// ---------------- problem constants ----------------
#define BATCH 8192
#define DIM   256
#define MROWS 64
#define NCOLS 64
#define MUNITS (MROWS * NCOLS)   // 4096

// argmin-GEMM tiling
#define BT 64          // batch rows per block
#define MT 64          // m units per chunk
#define NCHUNK (MUNITS / MT)   // 64
#define ARGMIN_SMEM (2 * 256 * 64 * 4)  // Xs + Ws, 131072 bytes

// ---------------- device scratch (no allocation allowed) ----------------
__device__ float g_S[MUNITS * DIM];    // per-node scatter sums
__device__ float g_T1[MUNITS * DIM];   // row-convolved sums
__device__ float g_cnt[MUNITS];        // per-node counts
__device__ float g_c1[MUNITS];         // row-convolved counts
__device__ float g_wnorm[MUNITS];      // ||w_m||^2
__device__ float g_t[64];              // t[d] = exp(-d^2/denom)
__device__ float g_alpha;
__device__ int   g_bmu[BATCH];

// ---------------- prep: epoch-dependent scalars + exp table ----------------
__global__ void k_prep(const int* __restrict__ epoch_p) {
    float ep = (float)(*epoch_p);
    float radius = 32.0f - ep * (31.0f / 99.0f);
    float alpha  = 0.1f * (1.0f - ep / 100.0f);
    float hs = radius * 0.5f;
    float denom = 2.0f * hs * hs;
    int j = threadIdx.x;
    if (j < 64) g_t[j] = expf(-((float)(j * j)) / denom);
    if (j == 0) g_alpha = alpha;
}

// ---------------- zero scratch (graph replays must be deterministic) -----
__global__ void k_zero() {
    int idx = blockIdx.x * 256 + threadIdx.x;
    if (idx < MUNITS * DIM) g_S[idx] = 0.0f;
    if (idx < MUNITS) g_cnt[idx] = 0.0f;
}

// ---------------- wnorm: ||w_m||^2 ----------------
__global__ void k_wnorm(const float* __restrict__ W) {
    int warp = threadIdx.x >> 5;
    int lane = threadIdx.x & 31;
    int m = blockIdx.x * 8 + warp;
    const float* row = W + (size_t)m * DIM;
    float s = 0.0f;
#pragma unroll
    for (int k = 0; k < DIM / 32; ++k) {
        float v = row[lane + k * 32];
        s += v * v;
    }
#pragma unroll
    for (int off = 16; off > 0; off >>= 1)
        s += __shfl_down_sync(0xFFFFFFFFu, s, off);
    if (lane == 0) g_wnorm[m] = s;
}

// ---------------- fused GEMM + argmin ----------------
// score(b,m) = ||w_m||^2 - 2 * x_b . w_m   (||x||^2 dropped: constant in m)
// Tiles stored d-major with quad rotation swizzle: logical quad q of row d
// lives at physical quad (q + (d>>2)) & 15.
__global__ __launch_bounds__(256) void k_argmin(
    const float* __restrict__ X, const float* __restrict__ W,
    int* __restrict__ bmu, float* __restrict__ outloc)
{
    extern __shared__ float sm[];
    float* Xs = sm;                // [256 rows][64 floats], swizzled
    float* Ws = sm + 256 * 64;     // [256 rows][64 floats], swizzled

    const int tid = threadIdx.x;
    const int tx = tid & 15;       // m-quad
    const int ty = tid >> 4;       // b-quad
    const int bbase = blockIdx.x * BT;

    // ---- load X tile (64 b x 256 d), transpose + swizzle ----
#pragma unroll
    for (int it = 0; it < 16; ++it) {
        int f = tid + it * 256;            // float4 index 0..4095
        int row = f >> 6;                  // b-local
        int d4 = f & 63;                   // d-quad
        float4 v = reinterpret_cast<const float4*>(X)[(size_t)(bbase + row) * 64 + d4];
        int qp = (((row >> 2) + d4) & 15);
        float* dst = Xs + d4 * 256 + qp * 4 + (row & 3);
        dst[0] = v.x; dst[64] = v.y; dst[128] = v.z; dst[192] = v.w;
    }

    float bestv[4];
    int   besti[4];
#pragma unroll
    for (int i = 0; i < 4; ++i) { bestv[i] = 3.4e38f; besti[i] = 0; }

    for (int ch = 0; ch < NCHUNK; ++ch) {
        __syncthreads();
        int mbase = ch * MT;
        // ---- load W chunk (64 m x 256 d), transpose + swizzle ----
#pragma unroll
        for (int it = 0; it < 16; ++it) {
            int f = tid + it * 256;
            int row = f >> 6;              // m-local
            int d4 = f & 63;
            float4 v = reinterpret_cast<const float4*>(W)[(size_t)(mbase + row) * 64 + d4];
            int qp = (((row >> 2) + d4) & 15);
            float* dst = Ws + d4 * 256 + qp * 4 + (row & 3);
            dst[0] = v.x; dst[64] = v.y; dst[128] = v.z; dst[192] = v.w;
        }
        __syncthreads();

        float acc[4][4];
#pragma unroll
        for (int i = 0; i < 4; ++i)
#pragma unroll
            for (int j = 0; j < 4; ++j) acc[i][j] = 0.0f;

#pragma unroll 4
        for (int d4 = 0; d4 < 64; ++d4) {
            int xq = ((ty + d4) & 15) * 4;
            int wq = ((tx + d4) & 15) * 4;
#pragma unroll
            for (int k = 0; k < 4; ++k) {
                float4 xv = *reinterpret_cast<const float4*>(Xs + d4 * 256 + k * 64 + xq);
                float4 wv = *reinterpret_cast<const float4*>(Ws + d4 * 256 + k * 64 + wq);
                acc[0][0] += xv.x * wv.x; acc[0][1] += xv.x * wv.y;
                acc[0][2] += xv.x * wv.z; acc[0][3] += xv.x * wv.w;
                acc[1][0] += xv.y * wv.x; acc[1][1] += xv.y * wv.y;
                acc[1][2] += xv.y * wv.z; acc[1][3] += xv.y * wv.w;
                acc[2][0] += xv.z * wv.x; acc[2][1] += xv.z * wv.y;
                acc[2][2] += xv.z * wv.z; acc[2][3] += xv.z * wv.w;
                acc[3][0] += xv.w * wv.x; acc[3][1] += xv.w * wv.y;
                acc[3][2] += xv.w * wv.z; acc[3][3] += xv.w * wv.w;
            }
        }

        // ---- scores + running argmin ----
#pragma unroll
        for (int j = 0; j < 4; ++j) {
            int m = mbase + tx * 4 + j;
            float wn = g_wnorm[m];
#pragma unroll
            for (int i = 0; i < 4; ++i) {
                float s = wn - 2.0f * acc[i][j];
                if (s < bestv[i]) { bestv[i] = s; besti[i] = m; }
            }
        }
    }

    __syncthreads();
    // ---- cross-thread reduction over tx (16 candidates per b-row) ----
    float* sv = Xs;                        // [64][16]
    int*   si = (int*)(Xs + 64 * 16);      // [64][16]
#pragma unroll
    for (int i = 0; i < 4; ++i) {
        sv[(ty * 4 + i) * 16 + tx] = bestv[i];
        si[(ty * 4 + i) * 16 + tx] = besti[i];
    }
    __syncthreads();
    if (tid < 64) {
        float bv = sv[tid * 16];
        int bi = si[tid * 16];
#pragma unroll
        for (int t = 1; t < 16; ++t) {
            float v = sv[tid * 16 + t];
            int idx = si[tid * 16 + t];
            if (v < bv || (v == bv && idx < bi)) { bv = v; bi = idx; }
        }
        int b = bbase + tid;
        g_bmu[b] = bi;
        if (outloc) {
            outloc[2 * b + 0] = (float)(bi >> 6);   // row = m // 64
            outloc[2 * b + 1] = (float)(bi & 63);   // col = m %  64
        }
    }
}

// ---------------- scatter: S[node] += x_b, cnt[node]++ ----------------
__global__ void k_scatter(const float* __restrict__ X) {
    int b = blockIdx.x;
    int node = g_bmu[b];
    atomicAdd(&g_S[(size_t)node * DIM + threadIdx.x], X[(size_t)b * DIM + threadIdx.x]);
    if (threadIdx.x == 0) atomicAdd(&g_cnt[node], 1.0f);
}

// ---------------- row convolution: T1[rm,cb,d] = sum_rb t[|rm-rb|] S[rb,cb,d]
__global__ void k_conv_row() {
    __shared__ float Ss[64][64];   // [rb][d']
    __shared__ float ts[64];
    int cb = blockIdx.x >> 2;
    int dbase = (blockIdx.x & 3) * 64;
    int tid = threadIdx.x;
    if (tid < 64) ts[tid] = g_t[tid];
#pragma unroll
    for (int i = 0; i < 16; ++i) {
        int idx = tid + i * 256;
        int rb = idx >> 6, dd = idx & 63;
        Ss[rb][dd] = g_S[(size_t)(rb * 64 + cb) * DIM + dbase + dd];
    }
    __syncthreads();
    int dd = tid & 63;
    int rm0 = (tid >> 6) * 16;
    float acc[16];
#pragma unroll
    for (int r = 0; r < 16; ++r) acc[r] = 0.0f;
    for (int rb = 0; rb < 64; ++rb) {
        float s = Ss[rb][dd];
#pragma unroll
        for (int r = 0; r < 16; ++r) {
            int di = rm0 + r - rb; di = di < 0 ? -di : di;
            acc[r] += ts[di] * s;
        }
    }
#pragma unroll
    for (int r = 0; r < 16; ++r)
        g_T1[(size_t)((rm0 + r) * 64 + cb) * DIM + dbase + dd] = acc[r];
}

// ---------------- count convolution (rows): c1[rm,cb] ----------------
__global__ void k_conv_cnt() {
    int gid = blockIdx.x * 256 + threadIdx.x;   // rm*64 + cb
    int rm = gid >> 6, cb = gid & 63;
    float acc = 0.0f;
    for (int rb = 0; rb < 64; ++rb) {
        int di = rm - rb; di = di < 0 ? -di : di;
        acc += g_t[di] * g_cnt[rb * 64 + cb];
    }
    g_c1[gid] = acc;
}

// ---------------- column convolution + divide -> new weights ----------------
__global__ void k_finalize(float* __restrict__ outW) {
    __shared__ float T1s[64][64];   // [cb][d']
    __shared__ float ts[64];
    __shared__ float c1s[64];
    __shared__ float dens[64];
    int rm = blockIdx.x >> 2;
    int dbase = (blockIdx.x & 3) * 64;
    int tid = threadIdx.x;
    if (tid < 64) { ts[tid] = g_t[tid]; c1s[tid] = g_c1[rm * 64 + tid]; }
#pragma unroll
    for (int i = 0; i < 16; ++i) {
        int idx = tid + i * 256;
        int cb = idx >> 6, dd = idx & 63;
        T1s[cb][dd] = g_T1[(size_t)(rm * 64 + cb) * DIM + dbase + dd];
    }
    __syncthreads();
    float alpha = g_alpha;
    if (tid < 64) {
        int cm = tid;
        float acc = 0.0f;
        for (int cb = 0; cb < 64; ++cb) {
            int di = cm - cb; di = di < 0 ? -di : di;
            acc += ts[di] * c1s[cb];
        }
        dens[cm] = alpha * acc + 1e-12f;
    }
    __syncthreads();
    int dd = tid & 63;
    int cm0 = (tid >> 6) * 16;
    float acc[16];
#pragma unroll
    for (int c = 0; c < 16; ++c) acc[c] = 0.0f;
    for (int cb = 0; cb < 64; ++cb) {
        float s = T1s[cb][dd];
#pragma unroll
        for (int c = 0; c < 16; ++c) {
            int di = cm0 + c - cb; di = di < 0 ? -di : di;
            acc[c] += ts[di] * s;
        }
    }
#pragma unroll
    for (int c = 0; c < 16; ++c) {
        int cm = cm0 + c;
        outW[(size_t)(rm * 64 + cm) * DIM + dbase + dd] = alpha * acc[c] / dens[cm];
    }
}

// ---------------- launch ----------------
extern "C" void kernel_launch(void* const* d_in, const int* in_sizes, int n_in,
                              void* d_out, int out_size) {
    const float* X = (const float*)d_in[0];
    const float* W = (const float*)d_in[1];
    const int* epoch = (const int*)d_in[2];

    float* out = (float*)d_out;
    float* outB = nullptr;   // bmu_locs as floats
    float* outW = nullptr;   // new_weights
    if (out_size >= BATCH * 2 + MUNITS * DIM) {
        outB = out;
        outW = out + (out_size - MUNITS * DIM);
    } else {
        outW = out;          // only weights fit
    }

    cudaFuncSetAttribute(k_argmin, cudaFuncAttributeMaxDynamicSharedMemorySize,
                         ARGMIN_SMEM);

    k_prep<<<1, 64>>>(epoch);
    k_zero<<<(MUNITS * DIM + 255) / 256, 256>>>();
    k_wnorm<<<MUNITS / 8, 256>>>(W);

    int* bmu_dev = nullptr;
    cudaGetSymbolAddress((void**)&bmu_dev, g_bmu);
    k_argmin<<<BATCH / BT, 256, ARGMIN_SMEM>>>(X, W, bmu_dev, outB);

    k_scatter<<<BATCH, 256>>>(X);
    k_conv_row<<<256, 256>>>();
    k_conv_cnt<<<MUNITS / 256, 256>>>();
    k_finalize<<<256, 256>>>(outW);
}

// round 8
// speedup vs baseline: 2.4695x; 2.4695x over previous
#include <cuda_runtime.h>
#include <cuda_bf16.h>
#include <cstdint>
#include <stdint.h>
#include <math.h>
#include <float.h>

// ---------------- problem constants ----------------
#define BATCH 8192
#define DIM   256
#define MROWS 64
#define NCOLS 64
#define MUNITS (MROWS * NCOLS)   // 4096
#define MARGIN 5.0f              // bf16 approx-score rescue margin

// k_scores tiling
#define MSPLIT 4
#define MPER (MUNITS / MSPLIT)   // 1024 m per CTA
#define MCHUNKS (MPER / 64)      // 16 chunks of 64 m
#define SM_X 0                   // X tile: 64 x 256 bf16 = 32768 B
#define SM_W0 32768              // W double buffer: 2 x 32768 B
#define SM_WBUF 32768
#define KS_SMEM (32768 + 2 * 32768)   // 98304

// ---------------- device scratch (no allocation allowed) ----------------
__device__ float g_scores[(size_t)BATCH * MUNITS];   // approx scores (134MB)
__device__ __nv_bfloat16 g_Xb[BATCH * DIM];
__device__ __nv_bfloat16 g_Wb[MUNITS * DIM];
__device__ float g_S[MUNITS * DIM];    // per-node scatter sums
__device__ float g_T1[MUNITS * DIM];   // row-convolved sums
__device__ float g_cnt[MUNITS];        // per-node counts
__device__ float g_c1[MUNITS];         // row-convolved counts
__device__ float g_wnorm[MUNITS];      // ||w_m||^2
__device__ float g_t[64];              // t[d] = exp(-d^2/denom)
__device__ float g_alpha;
__device__ int   g_bmu[BATCH];

// ---------------- PTX helpers (all plain sm_80+ features) ----------------
__device__ __forceinline__ uint32_t s2u(const void* p) {
    uint32_t a;
    asm("{ .reg .u64 t; cvta.to.shared.u64 t, %1; cvt.u32.u64 %0, t; }"
        : "=r"(a) : "l"(p));
    return a;
}

#define LDSM_X4(r0, r1, r2, r3, addr) \
    asm volatile("ldmatrix.sync.aligned.m8n8.x4.shared.b16 {%0,%1,%2,%3}, [%4];" \
        : "=r"(r0), "=r"(r1), "=r"(r2), "=r"(r3) : "r"(addr))

#define MMA16816(d, a0, a1, a2, a3, b0, b1) \
    asm volatile("mma.sync.aligned.m16n8k16.row.col.f32.bf16.bf16.f32 " \
        "{%0,%1,%2,%3}, {%4,%5,%6,%7}, {%8,%9}, {%0,%1,%2,%3};" \
        : "+f"((d)[0]), "+f"((d)[1]), "+f"((d)[2]), "+f"((d)[3]) \
        : "r"(a0), "r"(a1), "r"(a2), "r"(a3), "r"(b0), "r"(b1))

#define CP_ASYNC16(saddr, gaddr) \
    asm volatile("cp.async.ca.shared.global [%0], [%1], 16;" \
        :: "r"(saddr), "l"(gaddr))

// ---------------- prep: epoch-dependent scalars + exp table ----------------
__global__ void k_prep(const int* __restrict__ epoch_p) {
    float ep = (float)(*epoch_p);
    float radius = 32.0f - ep * (31.0f / 99.0f);
    float alpha  = 0.1f * (1.0f - ep / 100.0f);
    float hs = radius * 0.5f;
    float denom = 2.0f * hs * hs;
    int j = threadIdx.x;
    if (j < 64) g_t[j] = expf(-((float)(j * j)) / denom);
    if (j == 0) g_alpha = alpha;
}

__global__ void k_zero() {
    int idx = blockIdx.x * 256 + threadIdx.x;
    if (idx < MUNITS * DIM) g_S[idx] = 0.0f;
    if (idx < MUNITS) g_cnt[idx] = 0.0f;
}

__global__ void k_wnorm(const float* __restrict__ W) {
    int warp = threadIdx.x >> 5;
    int lane = threadIdx.x & 31;
    int m = blockIdx.x * 8 + warp;
    const float* row = W + (size_t)m * DIM;
    float s = 0.0f;
#pragma unroll
    for (int k = 0; k < DIM / 32; ++k) {
        float v = row[lane + k * 32];
        s += v * v;
    }
#pragma unroll
    for (int off = 16; off > 0; off >>= 1)
        s += __shfl_down_sync(0xFFFFFFFFu, s, off);
    if (lane == 0) g_wnorm[m] = s;
}

// ---------------- fp32 -> bf16 conversion ----------------
__global__ void k_cvtX(const float* __restrict__ X) {
    int i = blockIdx.x * 256 + threadIdx.x;
    float4 v = reinterpret_cast<const float4*>(X)[i];
    __nv_bfloat162* d = reinterpret_cast<__nv_bfloat162*>(g_Xb);
    d[2 * i]     = __floats2bfloat162_rn(v.x, v.y);
    d[2 * i + 1] = __floats2bfloat162_rn(v.z, v.w);
}
__global__ void k_cvtW(const float* __restrict__ W) {
    int i = blockIdx.x * 256 + threadIdx.x;
    float4 v = reinterpret_cast<const float4*>(W)[i];
    __nv_bfloat162* d = reinterpret_cast<__nv_bfloat162*>(g_Wb);
    d[2 * i]     = __floats2bfloat162_rn(v.x, v.y);
    d[2 * i + 1] = __floats2bfloat162_rn(v.z, v.w);
}

// ---------------- mma.sync score GEMM ----------------
// scores[b, m] = ||w_m||^2 - 2 * (x_b . w_m)   (bf16 in, fp32 accum)
// CTA: 256 thr = 8 warps (warp_b 0..3 x warp_m 0..1); b-tile 64, m-chunk 64.
// Smem tiles: row-major, 512B rows (256 bf16), 16B chunk swizzle c^(row&7).
__global__ __launch_bounds__(256) void k_scores() {
    extern __shared__ char sm[];
    const int tid = threadIdx.x;
    const int lane = tid & 31;
    const int wid = tid >> 5;
    const int warp_b = wid >> 1;
    const int warp_m = wid & 1;
    const int bbase = blockIdx.y * 64;
    const int mstart = blockIdx.x * MPER;

    // ---- load X tile 64 x 256 bf16, swizzled ----
#pragma unroll
    for (int it = 0; it < 8; ++it) {
        int idx = tid + it * 256;       // uint4 index, 2048 total
        int row = idx >> 5;
        int c = idx & 31;
        uint4 v = reinterpret_cast<const uint4*>(g_Xb)[(size_t)(bbase + row) * 32 + c];
        *reinterpret_cast<uint4*>(sm + SM_X + row * 512 + ((c ^ (row & 7)) << 4)) = v;
    }

    auto issueW = [&](int chunk, int buf) {
        const char* gb = reinterpret_cast<const char*>(g_Wb)
                       + (size_t)(mstart + chunk * 64) * 512;
        char* sb = sm + SM_W0 + buf * SM_WBUF;
#pragma unroll
        for (int it = 0; it < 8; ++it) {
            int idx = tid + it * 256;
            int row = idx >> 5;
            int c = idx & 31;
            uint32_t saddr = s2u(sb + row * 512 + ((c ^ (row & 7)) << 4));
            CP_ASYNC16(saddr, gb + row * 512 + c * 16);
        }
        asm volatile("cp.async.commit_group;" ::: "memory");
    };
    issueW(0, 0);

    // lane-derived ldmatrix bases
    const int l15 = lane & 15;
    const int hi = lane >> 4;
    const int rowA = warp_b * 16 + l15;
    const uint32_t aBase = s2u(sm + SM_X + rowA * 512);
    const int ra7 = rowA & 7;
    const int rowB0 = warp_m * 32 + l15;
    const int rowB1 = rowB0 + 16;
    const int rb07 = rowB0 & 7, rb17 = rowB1 & 7;
    const int b0off = rowB0 * 512, b1off = rowB1 * 512;

    const int brow = bbase + warp_b * 16 + (lane >> 2);
    const int mcol0 = warp_m * 32 + (lane & 3) * 2;

    for (int ch = 0; ch < MCHUNKS; ++ch) {
        int buf = ch & 1;
        if (ch + 1 < MCHUNKS) {
            issueW(ch + 1, buf ^ 1);
            asm volatile("cp.async.wait_group 1;" ::: "memory");
        } else {
            asm volatile("cp.async.wait_group 0;" ::: "memory");
        }
        __syncthreads();

        const uint32_t wBase0 = s2u(sm + SM_W0 + buf * SM_WBUF + b0off);
        const uint32_t wBase1 = s2u(sm + SM_W0 + buf * SM_WBUF + b1off);

        float acc[4][4];
#pragma unroll
        for (int i = 0; i < 4; ++i)
#pragma unroll
            for (int j = 0; j < 4; ++j) acc[i][j] = 0.0f;

#pragma unroll
        for (int kk = 0; kk < 16; ++kk) {
            int cc = kk * 2 + hi;
            uint32_t a0, a1, a2, a3;
            LDSM_X4(a0, a1, a2, a3, aBase + ((cc ^ ra7) << 4));
            uint32_t p0, p1, p2, p3, q0, q1, q2, q3;
            LDSM_X4(p0, p1, p2, p3, wBase0 + ((cc ^ rb07) << 4));
            LDSM_X4(q0, q1, q2, q3, wBase1 + ((cc ^ rb17) << 4));
            MMA16816(acc[0], a0, a1, a2, a3, p0, p2);   // n 0-7
            MMA16816(acc[1], a0, a1, a2, a3, p1, p3);   // n 8-15
            MMA16816(acc[2], a0, a1, a2, a3, q0, q2);   // n 16-23
            MMA16816(acc[3], a0, a1, a2, a3, q1, q3);   // n 24-31
        }

        // ---- epilogue: score = wnorm - 2*dot, write float2 pairs ----
        int mbase = mstart + ch * 64 + mcol0;
#pragma unroll
        for (int t = 0; t < 4; ++t) {
            int m = mbase + t * 8;
            float2 wn = *reinterpret_cast<const float2*>(&g_wnorm[m]);
            float2 s0, s1;
            s0.x = wn.x - 2.0f * acc[t][0]; s0.y = wn.y - 2.0f * acc[t][1];
            s1.x = wn.x - 2.0f * acc[t][2]; s1.y = wn.y - 2.0f * acc[t][3];
            *reinterpret_cast<float2*>(&g_scores[(size_t)brow * MUNITS + m]) = s0;
            *reinterpret_cast<float2*>(&g_scores[(size_t)(brow + 8) * MUNITS + m]) = s1;
        }
        __syncthreads();   // protect buf^1 before next issueW overwrite
    }
}

// ---------------- argmin with margin + exact fp32 rescue ----------------
__global__ __launch_bounds__(128) void k_bmu(const float* __restrict__ X,
                                             const float* __restrict__ W,
                                             float* __restrict__ outloc) {
    __shared__ __align__(16) float xs[256];
    __shared__ float redv[128];
    __shared__ int   redi[128];
    int b = blockIdx.x;
    int t = threadIdx.x;

    xs[t]       = X[(size_t)b * DIM + t];
    xs[t + 128] = X[(size_t)b * DIM + 128 + t];

    float v[32];
    const float4* sp = reinterpret_cast<const float4*>(g_scores + (size_t)b * MUNITS + t * 32);
    float amin = FLT_MAX;
#pragma unroll
    for (int i = 0; i < 8; ++i) {
        float4 q = sp[i];
        v[i * 4 + 0] = q.x; v[i * 4 + 1] = q.y; v[i * 4 + 2] = q.z; v[i * 4 + 3] = q.w;
        amin = fminf(amin, fminf(fminf(q.x, q.y), fminf(q.z, q.w)));
    }
    redv[t] = amin;
    __syncthreads();
#pragma unroll
    for (int s = 64; s > 0; s >>= 1) {
        if (t < s) redv[t] = fminf(redv[t], redv[t + s]);
        __syncthreads();
    }
    float thr = redv[0] + MARGIN;
    __syncthreads();

    float bestv = FLT_MAX;
    int   besti = 0x7FFFFFFF;
#pragma unroll
    for (int i = 0; i < 32; ++i) {
        if (v[i] <= thr) {
            int m = t * 32 + i;
            const float4* wp = reinterpret_cast<const float4*>(W + (size_t)m * DIM);
            const float4* xp = reinterpret_cast<const float4*>(xs);
            float a0 = 0.f, a1 = 0.f, a2 = 0.f, a3 = 0.f;
#pragma unroll 8
            for (int d = 0; d < 64; ++d) {
                float4 wv = __ldg(wp + d);
                float4 xv = xp[d];
                a0 += xv.x * wv.x; a1 += xv.y * wv.y;
                a2 += xv.z * wv.z; a3 += xv.w * wv.w;
            }
            float ex = g_wnorm[m] - 2.0f * ((a0 + a1) + (a2 + a3));
            if (ex < bestv || (ex == bestv && m < besti)) { bestv = ex; besti = m; }
        }
    }
    redv[t] = bestv;
    redi[t] = besti;
    __syncthreads();
#pragma unroll
    for (int s = 64; s > 0; s >>= 1) {
        if (t < s) {
            float ov = redv[t + s]; int oi = redi[t + s];
            if (ov < redv[t] || (ov == redv[t] && oi < redi[t])) {
                redv[t] = ov; redi[t] = oi;
            }
        }
        __syncthreads();
    }
    if (t == 0) {
        int bi = redi[0];
        g_bmu[b] = bi;
        if (outloc) {
            outloc[2 * b + 0] = (float)(bi >> 6);
            outloc[2 * b + 1] = (float)(bi & 63);
        }
    }
}

// ---------------- scatter: S[node] += x_b, cnt[node]++ ----------------
__global__ void k_scatter(const float* __restrict__ X) {
    int b = blockIdx.x;
    int node = g_bmu[b];
    atomicAdd(&g_S[(size_t)node * DIM + threadIdx.x], X[(size_t)b * DIM + threadIdx.x]);
    if (threadIdx.x == 0) atomicAdd(&g_cnt[node], 1.0f);
}

// ---------------- row convolution ----------------
__global__ void k_conv_row() {
    __shared__ float Ss[64][64];
    __shared__ float ts[64];
    int cb = blockIdx.x >> 2;
    int dbase = (blockIdx.x & 3) * 64;
    int tid = threadIdx.x;
    if (tid < 64) ts[tid] = g_t[tid];
#pragma unroll
    for (int i = 0; i < 16; ++i) {
        int idx = tid + i * 256;
        int rb = idx >> 6, dd = idx & 63;
        Ss[rb][dd] = g_S[(size_t)(rb * 64 + cb) * DIM + dbase + dd];
    }
    __syncthreads();
    int dd = tid & 63;
    int rm0 = (tid >> 6) * 16;
    float acc[16];
#pragma unroll
    for (int r = 0; r < 16; ++r) acc[r] = 0.0f;
    for (int rb = 0; rb < 64; ++rb) {
        float s = Ss[rb][dd];
#pragma unroll
        for (int r = 0; r < 16; ++r) {
            int di = rm0 + r - rb; di = di < 0 ? -di : di;
            acc[r] += ts[di] * s;
        }
    }
#pragma unroll
    for (int r = 0; r < 16; ++r)
        g_T1[(size_t)((rm0 + r) * 64 + cb) * DIM + dbase + dd] = acc[r];
}

__global__ void k_conv_cnt() {
    int gid = blockIdx.x * 256 + threadIdx.x;
    int rm = gid >> 6, cb = gid & 63;
    float acc = 0.0f;
    for (int rb = 0; rb < 64; ++rb) {
        int di = rm - rb; di = di < 0 ? -di : di;
        acc += g_t[di] * g_cnt[rb * 64 + cb];
    }
    g_c1[gid] = acc;
}

__global__ void k_finalize(float* __restrict__ outW) {
    __shared__ float T1s[64][64];
    __shared__ float ts[64];
    __shared__ float c1s[64];
    __shared__ float dens[64];
    int rm = blockIdx.x >> 2;
    int dbase = (blockIdx.x & 3) * 64;
    int tid = threadIdx.x;
    if (tid < 64) { ts[tid] = g_t[tid]; c1s[tid] = g_c1[rm * 64 + tid]; }
#pragma unroll
    for (int i = 0; i < 16; ++i) {
        int idx = tid + i * 256;
        int cb = idx >> 6, dd = idx & 63;
        T1s[cb][dd] = g_T1[(size_t)(rm * 64 + cb) * DIM + dbase + dd];
    }
    __syncthreads();
    float alpha = g_alpha;
    if (tid < 64) {
        int cm = tid;
        float acc = 0.0f;
        for (int cb = 0; cb < 64; ++cb) {
            int di = cm - cb; di = di < 0 ? -di : di;
            acc += ts[di] * c1s[cb];
        }
        dens[cm] = alpha * acc + 1e-12f;
    }
    __syncthreads();
    int dd = tid & 63;
    int cm0 = (tid >> 6) * 16;
    float acc[16];
#pragma unroll
    for (int c = 0; c < 16; ++c) acc[c] = 0.0f;
    for (int cb = 0; cb < 64; ++cb) {
        float s = T1s[cb][dd];
#pragma unroll
        for (int c = 0; c < 16; ++c) {
            int di = cm0 + c - cb; di = di < 0 ? -di : di;
            acc[c] += ts[di] * s;
        }
    }
#pragma unroll
    for (int c = 0; c < 16; ++c) {
        int cm = cm0 + c;
        outW[(size_t)(rm * 64 + cm) * DIM + dbase + dd] = alpha * acc[c] / dens[cm];
    }
}

// ---------------- launch ----------------
extern "C" void kernel_launch(void* const* d_in, const int* in_sizes, int n_in,
                              void* d_out, int out_size) {
    const float* X = (const float*)d_in[0];
    const float* W = (const float*)d_in[1];
    const int* epoch = (const int*)d_in[2];

    float* out = (float*)d_out;
    float* outB = nullptr;
    float* outW = nullptr;
    if (out_size >= BATCH * 2 + MUNITS * DIM) {
        outB = out;
        outW = out + (out_size - MUNITS * DIM);
    } else {
        outW = out;
    }

    static int smem_set = 0;
    if (!smem_set) {
        cudaFuncSetAttribute(k_scores, cudaFuncAttributeMaxDynamicSharedMemorySize,
                             KS_SMEM);
        smem_set = 1;
    }

    k_prep<<<1, 64>>>(epoch);
    k_zero<<<(MUNITS * DIM + 255) / 256, 256>>>();
    k_wnorm<<<MUNITS / 8, 256>>>(W);
    k_cvtX<<<BATCH * DIM / 4 / 256, 256>>>(X);
    k_cvtW<<<MUNITS * DIM / 4 / 256, 256>>>(W);

    k_scores<<<dim3(MSPLIT, BATCH / 64), 256, KS_SMEM>>>();
    k_bmu<<<BATCH, 128>>>(X, W, outB);

    k_scatter<<<BATCH, 256>>>(X);
    k_conv_row<<<256, 256>>>();
    k_conv_cnt<<<MUNITS / 256, 256>>>();
    k_finalize<<<256, 256>>>(outW);
}

// round 9
// speedup vs baseline: 2.7260x; 1.1039x over previous
#include <cuda_runtime.h>
#include <cuda_bf16.h>
#include <cuda_fp16.h>
#include <cstdint>
#include <stdint.h>
#include <math.h>
#include <float.h>

// ---------------- problem constants ----------------
#define BATCH 8192
#define DIM   256
#define MROWS 64
#define NCOLS 64
#define MUNITS (MROWS * NCOLS)   // 4096
#define MARGIN 6.0f              // bf16-GEMM + fp16-store rescue margin

// k_scores tiling
#define MSPLIT 4
#define MPER (MUNITS / MSPLIT)   // 1024 m per CTA
#define MCHUNKS (MPER / 64)      // 16 chunks of 64 m
#define SM_X 0                   // X tile: 64 x 256 bf16 = 32768 B
#define SM_W0 32768              // W double buffer: 2 x 32768 B
#define SM_WBUF 32768
#define KS_SMEM (32768 + 2 * 32768)   // 98304

// ---------------- device scratch (no allocation allowed) ----------------
__device__ __half g_scores[(size_t)BATCH * MUNITS];  // approx scores (67MB)
__device__ __nv_bfloat16 g_Xb[BATCH * DIM];
__device__ __nv_bfloat16 g_Wb[MUNITS * DIM];
__device__ float g_S[MUNITS * DIM];    // per-node scatter sums
__device__ float g_T1[MUNITS * DIM];   // row-convolved sums
__device__ float g_cnt[MUNITS];        // per-node counts
__device__ float g_c1[MUNITS];         // row-convolved counts
__device__ float g_wnorm[MUNITS];      // ||w_m||^2
__device__ float g_t[64];              // t[d] = exp(-d^2/denom)
__device__ float g_alpha;

// ---------------- PTX helpers (all plain sm_80+ features) ----------------
__device__ __forceinline__ uint32_t s2u(const void* p) {
    uint32_t a;
    asm("{ .reg .u64 t; cvta.to.shared.u64 t, %1; cvt.u32.u64 %0, t; }"
        : "=r"(a) : "l"(p));
    return a;
}

#define LDSM_X4(r0, r1, r2, r3, addr) \
    asm volatile("ldmatrix.sync.aligned.m8n8.x4.shared.b16 {%0,%1,%2,%3}, [%4];" \
        : "=r"(r0), "=r"(r1), "=r"(r2), "=r"(r3) : "r"(addr))

#define MMA16816(d, a0, a1, a2, a3, b0, b1) \
    asm volatile("mma.sync.aligned.m16n8k16.row.col.f32.bf16.bf16.f32 " \
        "{%0,%1,%2,%3}, {%4,%5,%6,%7}, {%8,%9}, {%0,%1,%2,%3};" \
        : "+f"((d)[0]), "+f"((d)[1]), "+f"((d)[2]), "+f"((d)[3]) \
        : "r"(a0), "r"(a1), "r"(a2), "r"(a3), "r"(b0), "r"(b1))

#define CP_ASYNC16(saddr, gaddr) \
    asm volatile("cp.async.ca.shared.global [%0], [%1], 16;" \
        :: "r"(saddr), "l"(gaddr))

// ---------------- prep: epoch-dependent scalars + exp table ----------------
__global__ void k_prep(const int* __restrict__ epoch_p) {
    float ep = (float)(*epoch_p);
    float radius = 32.0f - ep * (31.0f / 99.0f);
    float alpha  = 0.1f * (1.0f - ep / 100.0f);
    float hs = radius * 0.5f;
    float denom = 2.0f * hs * hs;
    int j = threadIdx.x;
    if (j < 64) g_t[j] = expf(-((float)(j * j)) / denom);
    if (j == 0) g_alpha = alpha;
}

__global__ void k_zero() {
    int idx = blockIdx.x * 256 + threadIdx.x;
    if (idx < MUNITS * DIM) g_S[idx] = 0.0f;
    if (idx < MUNITS) g_cnt[idx] = 0.0f;
}

__global__ void k_wnorm(const float* __restrict__ W) {
    int warp = threadIdx.x >> 5;
    int lane = threadIdx.x & 31;
    int m = blockIdx.x * 8 + warp;
    const float* row = W + (size_t)m * DIM;
    float s = 0.0f;
#pragma unroll
    for (int k = 0; k < DIM / 32; ++k) {
        float v = row[lane + k * 32];
        s += v * v;
    }
#pragma unroll
    for (int off = 16; off > 0; off >>= 1)
        s += __shfl_down_sync(0xFFFFFFFFu, s, off);
    if (lane == 0) g_wnorm[m] = s;
}

// ---------------- fp32 -> bf16 conversion ----------------
__global__ void k_cvtX(const float* __restrict__ X) {
    int i = blockIdx.x * 256 + threadIdx.x;
    float4 v = reinterpret_cast<const float4*>(X)[i];
    __nv_bfloat162* d = reinterpret_cast<__nv_bfloat162*>(g_Xb);
    d[2 * i]     = __floats2bfloat162_rn(v.x, v.y);
    d[2 * i + 1] = __floats2bfloat162_rn(v.z, v.w);
}
__global__ void k_cvtW(const float* __restrict__ W) {
    int i = blockIdx.x * 256 + threadIdx.x;
    float4 v = reinterpret_cast<const float4*>(W)[i];
    __nv_bfloat162* d = reinterpret_cast<__nv_bfloat162*>(g_Wb);
    d[2 * i]     = __floats2bfloat162_rn(v.x, v.y);
    d[2 * i + 1] = __floats2bfloat162_rn(v.z, v.w);
}

// ---------------- mma.sync score GEMM ----------------
// scores[b, m] = ||w_m||^2 - 2 * (x_b . w_m)   (bf16 in, fp32 accum, fp16 out)
// CTA: 256 thr = 8 warps (warp_b 0..3 x warp_m 0..1); b-tile 64, m-chunk 64.
// Smem tiles: row-major, 512B rows (256 bf16), 16B chunk swizzle c^(row&7).
__global__ __launch_bounds__(256) void k_scores() {
    extern __shared__ char sm[];
    const int tid = threadIdx.x;
    const int lane = tid & 31;
    const int wid = tid >> 5;
    const int warp_b = wid >> 1;
    const int warp_m = wid & 1;
    const int bbase = blockIdx.y * 64;
    const int mstart = blockIdx.x * MPER;

    // ---- load X tile 64 x 256 bf16, swizzled ----
#pragma unroll
    for (int it = 0; it < 8; ++it) {
        int idx = tid + it * 256;       // uint4 index, 2048 total
        int row = idx >> 5;
        int c = idx & 31;
        uint4 v = reinterpret_cast<const uint4*>(g_Xb)[(size_t)(bbase + row) * 32 + c];
        *reinterpret_cast<uint4*>(sm + SM_X + row * 512 + ((c ^ (row & 7)) << 4)) = v;
    }

    auto issueW = [&](int chunk, int buf) {
        const char* gb = reinterpret_cast<const char*>(g_Wb)
                       + (size_t)(mstart + chunk * 64) * 512;
        char* sb = sm + SM_W0 + buf * SM_WBUF;
#pragma unroll
        for (int it = 0; it < 8; ++it) {
            int idx = tid + it * 256;
            int row = idx >> 5;
            int c = idx & 31;
            uint32_t saddr = s2u(sb + row * 512 + ((c ^ (row & 7)) << 4));
            CP_ASYNC16(saddr, gb + row * 512 + c * 16);
        }
        asm volatile("cp.async.commit_group;" ::: "memory");
    };
    issueW(0, 0);

    // lane-derived ldmatrix bases
    const int l15 = lane & 15;
    const int hi = lane >> 4;
    const int rowA = warp_b * 16 + l15;
    const uint32_t aBase = s2u(sm + SM_X + rowA * 512);
    const int ra7 = rowA & 7;
    const int rowB0 = warp_m * 32 + l15;
    const int rowB1 = rowB0 + 16;
    const int rb07 = rowB0 & 7, rb17 = rowB1 & 7;
    const int b0off = rowB0 * 512, b1off = rowB1 * 512;

    const int brow = bbase + warp_b * 16 + (lane >> 2);
    const int mcol0 = warp_m * 32 + (lane & 3) * 2;

    for (int ch = 0; ch < MCHUNKS; ++ch) {
        int buf = ch & 1;
        if (ch + 1 < MCHUNKS) {
            issueW(ch + 1, buf ^ 1);
            asm volatile("cp.async.wait_group 1;" ::: "memory");
        } else {
            asm volatile("cp.async.wait_group 0;" ::: "memory");
        }
        __syncthreads();

        const uint32_t wBase0 = s2u(sm + SM_W0 + buf * SM_WBUF + b0off);
        const uint32_t wBase1 = s2u(sm + SM_W0 + buf * SM_WBUF + b1off);

        float acc[4][4];
#pragma unroll
        for (int i = 0; i < 4; ++i)
#pragma unroll
            for (int j = 0; j < 4; ++j) acc[i][j] = 0.0f;

#pragma unroll
        for (int kk = 0; kk < 16; ++kk) {
            int cc = kk * 2 + hi;
            uint32_t a0, a1, a2, a3;
            LDSM_X4(a0, a1, a2, a3, aBase + ((cc ^ ra7) << 4));
            uint32_t p0, p1, p2, p3, q0, q1, q2, q3;
            LDSM_X4(p0, p1, p2, p3, wBase0 + ((cc ^ rb07) << 4));
            LDSM_X4(q0, q1, q2, q3, wBase1 + ((cc ^ rb17) << 4));
            MMA16816(acc[0], a0, a1, a2, a3, p0, p2);   // n 0-7
            MMA16816(acc[1], a0, a1, a2, a3, p1, p3);   // n 8-15
            MMA16816(acc[2], a0, a1, a2, a3, q0, q2);   // n 16-23
            MMA16816(acc[3], a0, a1, a2, a3, q1, q3);   // n 24-31
        }

        // ---- epilogue: score = wnorm - 2*dot, write half2 pairs ----
        int mbase = mstart + ch * 64 + mcol0;
#pragma unroll
        for (int t = 0; t < 4; ++t) {
            int m = mbase + t * 8;
            float2 wn = *reinterpret_cast<const float2*>(&g_wnorm[m]);
            __half2 s0 = __floats2half2_rn(wn.x - 2.0f * acc[t][0],
                                           wn.y - 2.0f * acc[t][1]);
            __half2 s1 = __floats2half2_rn(wn.x - 2.0f * acc[t][2],
                                           wn.y - 2.0f * acc[t][3]);
            *reinterpret_cast<__half2*>(&g_scores[(size_t)brow * MUNITS + m]) = s0;
            *reinterpret_cast<__half2*>(&g_scores[(size_t)(brow + 8) * MUNITS + m]) = s1;
        }
        __syncthreads();   // protect buf^1 before next issueW overwrite
    }
}

// ---------------- argmin + exact fp32 rescue + fused scatter ----------------
__global__ __launch_bounds__(128) void k_bmu(const float* __restrict__ X,
                                             const float* __restrict__ W,
                                             float* __restrict__ outloc) {
    __shared__ __align__(16) float xs[256];
    __shared__ float redv[128];
    __shared__ int   redi[128];
    __shared__ int   s_node;
    int b = blockIdx.x;
    int t = threadIdx.x;

    xs[t]       = X[(size_t)b * DIM + t];
    xs[t + 128] = X[(size_t)b * DIM + 128 + t];

    // each thread owns 32 contiguous approx scores (fp16), kept as fp32 regs
    float v[32];
    const uint4* sp = reinterpret_cast<const uint4*>(g_scores + (size_t)b * MUNITS + t * 32);
    float amin = FLT_MAX;
#pragma unroll
    for (int i = 0; i < 4; ++i) {
        uint4 q = sp[i];
        const __half2* h = reinterpret_cast<const __half2*>(&q);
#pragma unroll
        for (int j = 0; j < 4; ++j) {
            float2 f = __half22float2(h[j]);
            v[i * 8 + j * 2 + 0] = f.x;
            v[i * 8 + j * 2 + 1] = f.y;
            amin = fminf(amin, fminf(f.x, f.y));
        }
    }
    redv[t] = amin;
    __syncthreads();
#pragma unroll
    for (int s = 64; s > 0; s >>= 1) {
        if (t < s) redv[t] = fminf(redv[t], redv[t + s]);
        __syncthreads();
    }
    float thr = redv[0] + MARGIN;
    __syncthreads();

    float bestv = FLT_MAX;
    int   besti = 0x7FFFFFFF;
#pragma unroll
    for (int i = 0; i < 32; ++i) {
        if (v[i] <= thr) {
            int m = t * 32 + i;
            const float4* wp = reinterpret_cast<const float4*>(W + (size_t)m * DIM);
            const float4* xp = reinterpret_cast<const float4*>(xs);
            float a0 = 0.f, a1 = 0.f, a2 = 0.f, a3 = 0.f;
#pragma unroll 8
            for (int d = 0; d < 64; ++d) {
                float4 wv = __ldg(wp + d);
                float4 xv = xp[d];
                a0 += xv.x * wv.x; a1 += xv.y * wv.y;
                a2 += xv.z * wv.z; a3 += xv.w * wv.w;
            }
            float ex = g_wnorm[m] - 2.0f * ((a0 + a1) + (a2 + a3));
            if (ex < bestv || (ex == bestv && m < besti)) { bestv = ex; besti = m; }
        }
    }
    redv[t] = bestv;
    redi[t] = besti;
    __syncthreads();
#pragma unroll
    for (int s = 64; s > 0; s >>= 1) {
        if (t < s) {
            float ov = redv[t + s]; int oi = redi[t + s];
            if (ov < redv[t] || (ov == redv[t] && oi < redi[t])) {
                redv[t] = ov; redi[t] = oi;
            }
        }
        __syncthreads();
    }
    if (t == 0) {
        int bi = redi[0];
        s_node = bi;
        if (outloc) {
            outloc[2 * b + 0] = (float)(bi >> 6);
            outloc[2 * b + 1] = (float)(bi & 63);
        }
        atomicAdd(&g_cnt[bi], 1.0f);
    }
    __syncthreads();
    // ---- fused scatter: S[node] += x_b ----
    int node = s_node;
    atomicAdd(&g_S[(size_t)node * DIM + t],       xs[t]);
    atomicAdd(&g_S[(size_t)node * DIM + t + 128], xs[t + 128]);
}

// ---------------- row convolution ----------------
__global__ void k_conv_row() {
    __shared__ float Ss[64][64];
    __shared__ float ts[64];
    int cb = blockIdx.x >> 2;
    int dbase = (blockIdx.x & 3) * 64;
    int tid = threadIdx.x;
    if (tid < 64) ts[tid] = g_t[tid];
#pragma unroll
    for (int i = 0; i < 16; ++i) {
        int idx = tid + i * 256;
        int rb = idx >> 6, dd = idx & 63;
        Ss[rb][dd] = g_S[(size_t)(rb * 64 + cb) * DIM + dbase + dd];
    }
    __syncthreads();
    int dd = tid & 63;
    int rm0 = (tid >> 6) * 16;
    float acc[16];
#pragma unroll
    for (int r = 0; r < 16; ++r) acc[r] = 0.0f;
    for (int rb = 0; rb < 64; ++rb) {
        float s = Ss[rb][dd];
#pragma unroll
        for (int r = 0; r < 16; ++r) {
            int di = rm0 + r - rb; di = di < 0 ? -di : di;
            acc[r] += ts[di] * s;
        }
    }
#pragma unroll
    for (int r = 0; r < 16; ++r)
        g_T1[(size_t)((rm0 + r) * 64 + cb) * DIM + dbase + dd] = acc[r];
}

__global__ void k_conv_cnt() {
    int gid = blockIdx.x * 256 + threadIdx.x;
    int rm = gid >> 6, cb = gid & 63;
    float acc = 0.0f;
    for (int rb = 0; rb < 64; ++rb) {
        int di = rm - rb; di = di < 0 ? -di : di;
        acc += g_t[di] * g_cnt[rb * 64 + cb];
    }
    g_c1[gid] = acc;
}

__global__ void k_finalize(float* __restrict__ outW) {
    __shared__ float T1s[64][64];
    __shared__ float ts[64];
    __shared__ float c1s[64];
    __shared__ float dens[64];
    int rm = blockIdx.x >> 2;
    int dbase = (blockIdx.x & 3) * 64;
    int tid = threadIdx.x;
    if (tid < 64) { ts[tid] = g_t[tid]; c1s[tid] = g_c1[rm * 64 + tid]; }
#pragma unroll
    for (int i = 0; i < 16; ++i) {
        int idx = tid + i * 256;
        int cb = idx >> 6, dd = idx & 63;
        T1s[cb][dd] = g_T1[(size_t)(rm * 64 + cb) * DIM + dbase + dd];
    }
    __syncthreads();
    float alpha = g_alpha;
    if (tid < 64) {
        int cm = tid;
        float acc = 0.0f;
        for (int cb = 0; cb < 64; ++cb) {
            int di = cm - cb; di = di < 0 ? -di : di;
            acc += ts[di] * c1s[cb];
        }
        dens[cm] = alpha * acc + 1e-12f;
    }
    __syncthreads();
    int dd = tid & 63;
    int cm0 = (tid >> 6) * 16;
    float acc[16];
#pragma unroll
    for (int c = 0; c < 16; ++c) acc[c] = 0.0f;
    for (int cb = 0; cb < 64; ++cb) {
        float s = T1s[cb][dd];
#pragma unroll
        for (int c = 0; c < 16; ++c) {
            int di = cm0 + c - cb; di = di < 0 ? -di : di;
            acc[c] += ts[di] * s;
        }
    }
#pragma unroll
    for (int c = 0; c < 16; ++c) {
        int cm = cm0 + c;
        outW[(size_t)(rm * 64 + cm) * DIM + dbase + dd] = alpha * acc[c] / dens[cm];
    }
}

// ---------------- launch ----------------
extern "C" void kernel_launch(void* const* d_in, const int* in_sizes, int n_in,
                              void* d_out, int out_size) {
    const float* X = (const float*)d_in[0];
    const float* W = (const float*)d_in[1];
    const int* epoch = (const int*)d_in[2];

    float* out = (float*)d_out;
    float* outB = nullptr;
    float* outW = nullptr;
    if (out_size >= BATCH * 2 + MUNITS * DIM) {
        outB = out;
        outW = out + (out_size - MUNITS * DIM);
    } else {
        outW = out;
    }

    static int smem_set = 0;
    if (!smem_set) {
        cudaFuncSetAttribute(k_scores, cudaFuncAttributeMaxDynamicSharedMemorySize,
                             KS_SMEM);
        smem_set = 1;
    }

    k_prep<<<1, 64>>>(epoch);
    k_zero<<<(MUNITS * DIM + 255) / 256, 256>>>();
    k_wnorm<<<MUNITS / 8, 256>>>(W);
    k_cvtX<<<BATCH * DIM / 4 / 256, 256>>>(X);
    k_cvtW<<<MUNITS * DIM / 4 / 256, 256>>>(W);

    k_scores<<<dim3(MSPLIT, BATCH / 64), 256, KS_SMEM>>>();
    k_bmu<<<BATCH, 128>>>(X, W, outB);

    k_conv_row<<<256, 256>>>();
    k_conv_cnt<<<MUNITS / 256, 256>>>();
    k_finalize<<<256, 256>>>(outW);
}

// round 11
// speedup vs baseline: 2.8852x; 1.0584x over previous
#include <cuda_runtime.h>
#include <cuda_bf16.h>
#include <cuda_fp16.h>
#include <cstdint>
#include <stdint.h>
#include <math.h>
#include <float.h>

// ---------------- problem constants ----------------
#define BATCH 8192
#define DIM   256
#define MROWS 64
#define NCOLS 64
#define MUNITS (MROWS * NCOLS)   // 4096
#define MARGIN 6.0f              // bf16-GEMM + fp16-store rescue margin

// k_scores tiling: BT=128 batch rows, MSPLIT=2 -> 128 CTAs (one wave)
#define MSPLIT 2
#define MPER (MUNITS / MSPLIT)   // 2048 m per CTA
#define MCHUNKS (MPER / 64)      // 32 chunks of 64 m
#define SM_X 0                   // X tile: 128 x 256 bf16 = 65536 B
#define SM_W0 65536              // W double buffer: 2 x 32768 B
#define SM_WBUF 32768
#define KS_SMEM (65536 + 2 * 32768)   // 131072

// ---------------- device scratch (no allocation allowed) ----------------
__device__ __half g_scores[(size_t)BATCH * MUNITS];  // approx scores (67MB)
__device__ __nv_bfloat16 g_Xb[BATCH * DIM];
__device__ __nv_bfloat16 g_Wb[MUNITS * DIM];
__device__ float g_S[MUNITS * DIM];    // per-node scatter sums
__device__ float g_T1[MUNITS * DIM];   // row-convolved sums
__device__ float g_cnt[MUNITS];        // per-node counts
__device__ float g_c1[MUNITS];         // row-convolved counts
__device__ float g_wnorm[MUNITS];      // ||w_m||^2
__device__ float g_t[64];              // t[d] = exp(-d^2/denom)
__device__ float g_alpha;

// ---------------- PTX helpers (all plain sm_80+ features) ----------------
__device__ __forceinline__ uint32_t s2u(const void* p) {
    uint32_t a;
    asm("{ .reg .u64 t; cvta.to.shared.u64 t, %1; cvt.u32.u64 %0, t; }"
        : "=r"(a) : "l"(p));
    return a;
}

#define LDSM_X4(r0, r1, r2, r3, addr) \
    asm volatile("ldmatrix.sync.aligned.m8n8.x4.shared.b16 {%0,%1,%2,%3}, [%4];" \
        : "=r"(r0), "=r"(r1), "=r"(r2), "=r"(r3) : "r"(addr))

#define MMA16816(d, a0, a1, a2, a3, b0, b1) \
    asm volatile("mma.sync.aligned.m16n8k16.row.col.f32.bf16.bf16.f32 " \
        "{%0,%1,%2,%3}, {%4,%5,%6,%7}, {%8,%9}, {%0,%1,%2,%3};" \
        : "+f"((d)[0]), "+f"((d)[1]), "+f"((d)[2]), "+f"((d)[3]) \
        : "r"(a0), "r"(a1), "r"(a2), "r"(a3), "r"(b0), "r"(b1))

#define CP_ASYNC16(saddr, gaddr) \
    asm volatile("cp.async.ca.shared.global [%0], [%1], 16;" \
        :: "r"(saddr), "l"(gaddr))

// ---------------- mega-prep: cvtX + cvtW + wnorm + zero + exp table -------
// blocks [0, 2048):     cvtX
// blocks [2048, 3072):  cvtW + wnorm (4 rows/block) + zero g_S slice
// block  3072:          exp table + alpha + zero g_cnt
__global__ __launch_bounds__(256) void k_pre(const float* __restrict__ X,
                                             const float* __restrict__ W,
                                             const int* __restrict__ epoch_p) {
    __shared__ float sred[256];
    int blk = blockIdx.x;
    int tid = threadIdx.x;

    if (blk < 2048) {                      // ---- cvtX ----
        int i = blk * 256 + tid;
        float4 v = reinterpret_cast<const float4*>(X)[i];
        __nv_bfloat162* d = reinterpret_cast<__nv_bfloat162*>(g_Xb);
        d[2 * i]     = __floats2bfloat162_rn(v.x, v.y);
        d[2 * i + 1] = __floats2bfloat162_rn(v.z, v.w);
    } else if (blk < 3072) {               // ---- cvtW + wnorm + zero S ----
        int j = blk - 2048;                // 0..1023, covers W rows 4j..4j+3
        int i = j * 256 + tid;             // float4 index
        float4 v = reinterpret_cast<const float4*>(W)[i];
        __nv_bfloat162* d = reinterpret_cast<__nv_bfloat162*>(g_Wb);
        d[2 * i]     = __floats2bfloat162_rn(v.x, v.y);
        d[2 * i + 1] = __floats2bfloat162_rn(v.z, v.w);
        // zero g_S slice (1024 floats per block)
        reinterpret_cast<float4*>(g_S)[i] = make_float4(0.f, 0.f, 0.f, 0.f);
        // wnorm: fp32 dot of own 4 elems, reduce per 64-thread row group
        sred[tid] = v.x * v.x + v.y * v.y + v.z * v.z + v.w * v.w;
        __syncthreads();
#pragma unroll
        for (int s = 32; s > 0; s >>= 1) {
            if ((tid & 63) < s) sred[tid] += sred[tid + s];
            __syncthreads();
        }
        if ((tid & 63) == 0) g_wnorm[4 * j + (tid >> 6)] = sred[tid];
    } else {                               // ---- table + cnt zero ----
        if (tid < 64) {
            float ep = (float)(*epoch_p);
            float radius = 32.0f - ep * (31.0f / 99.0f);
            float hs = radius * 0.5f;
            float denom = 2.0f * hs * hs;
            g_t[tid] = expf(-((float)(tid * tid)) / denom);
            if (tid == 0) g_alpha = 0.1f * (1.0f - ep / 100.0f);
        }
#pragma unroll
        for (int k = 0; k < 16; ++k) g_cnt[tid + k * 256] = 0.0f;
    }
}

// ---------------- mma.sync score GEMM ----------------
// scores[b, m] = ||w_m||^2 - 2 * (x_b . w_m)   (bf16 in, fp32 accum, fp16 out)
// CTA: 256 thr = 8 warps (warp_b 0..3 x warp_m 0..1); b-tile 128, m-chunk 64.
// Warp tile: 32 b (two 16-row MMA tiles) x 32 m.
__global__ __launch_bounds__(256) void k_scores() {
    extern __shared__ char sm[];
    const int tid = threadIdx.x;
    const int lane = tid & 31;
    const int wid = tid >> 5;
    const int warp_b = wid >> 1;
    const int warp_m = wid & 1;
    const int bbase = blockIdx.y * 128;
    const int mstart = blockIdx.x * MPER;

    // ---- load X tile 128 x 256 bf16, swizzled ----
#pragma unroll
    for (int it = 0; it < 16; ++it) {
        int idx = tid + it * 256;       // uint4 index, 4096 total
        int row = idx >> 5;
        int c = idx & 31;
        uint4 v = reinterpret_cast<const uint4*>(g_Xb)[(size_t)(bbase + row) * 32 + c];
        *reinterpret_cast<uint4*>(sm + SM_X + row * 512 + ((c ^ (row & 7)) << 4)) = v;
    }

    auto issueW = [&](int chunk, int buf) {
        const char* gb = reinterpret_cast<const char*>(g_Wb)
                       + (size_t)(mstart + chunk * 64) * 512;
        char* sb = sm + SM_W0 + buf * SM_WBUF;
#pragma unroll
        for (int it = 0; it < 8; ++it) {
            int idx = tid + it * 256;
            int row = idx >> 5;
            int c = idx & 31;
            uint32_t saddr = s2u(sb + row * 512 + ((c ^ (row & 7)) << 4));
            CP_ASYNC16(saddr, gb + row * 512 + c * 16);
        }
        asm volatile("cp.async.commit_group;" ::: "memory");
    };
    issueW(0, 0);

    // lane-derived ldmatrix bases (all row&7 terms equal l15&7)
    const int l15 = lane & 15;
    const int hi = lane >> 4;
    const int s7 = l15 & 7;
    const uint32_t aBase0 = s2u(sm + SM_X + (warp_b * 32 + l15) * 512);
    const uint32_t aBase1 = s2u(sm + SM_X + (warp_b * 32 + 16 + l15) * 512);
    const int b0off = (warp_m * 32 + l15) * 512;
    const int b1off = (warp_m * 32 + 16 + l15) * 512;

    const int brow0 = bbase + warp_b * 32 + (lane >> 2);
    const int mcol0 = warp_m * 32 + (lane & 3) * 2;

    for (int ch = 0; ch < MCHUNKS; ++ch) {
        int buf = ch & 1;
        if (ch + 1 < MCHUNKS) {
            issueW(ch + 1, buf ^ 1);
            asm volatile("cp.async.wait_group 1;" ::: "memory");
        } else {
            asm volatile("cp.async.wait_group 0;" ::: "memory");
        }
        __syncthreads();

        const uint32_t wBase0 = s2u(sm + SM_W0 + buf * SM_WBUF + b0off);
        const uint32_t wBase1 = s2u(sm + SM_W0 + buf * SM_WBUF + b1off);

        float acc[2][4][4];
#pragma unroll
        for (int rt = 0; rt < 2; ++rt)
#pragma unroll
            for (int i = 0; i < 4; ++i)
#pragma unroll
                for (int j = 0; j < 4; ++j) acc[rt][i][j] = 0.0f;

#pragma unroll
        for (int kk = 0; kk < 16; ++kk) {
            int off = (((kk * 2 + hi) ^ s7) << 4);
            uint32_t a0, a1, a2, a3, c0, c1, c2, c3;
            LDSM_X4(a0, a1, a2, a3, aBase0 + off);
            LDSM_X4(c0, c1, c2, c3, aBase1 + off);
            uint32_t p0, p1, p2, p3, q0, q1, q2, q3;
            LDSM_X4(p0, p1, p2, p3, wBase0 + off);
            LDSM_X4(q0, q1, q2, q3, wBase1 + off);
            MMA16816(acc[0][0], a0, a1, a2, a3, p0, p2);
            MMA16816(acc[0][1], a0, a1, a2, a3, p1, p3);
            MMA16816(acc[0][2], a0, a1, a2, a3, q0, q2);
            MMA16816(acc[0][3], a0, a1, a2, a3, q1, q3);
            MMA16816(acc[1][0], c0, c1, c2, c3, p0, p2);
            MMA16816(acc[1][1], c0, c1, c2, c3, p1, p3);
            MMA16816(acc[1][2], c0, c1, c2, c3, q0, q2);
            MMA16816(acc[1][3], c0, c1, c2, c3, q1, q3);
        }

        // ---- epilogue: score = wnorm - 2*dot, write half2 pairs ----
        int mbase = mstart + ch * 64 + mcol0;
#pragma unroll
        for (int rt = 0; rt < 2; ++rt) {
            int br = brow0 + rt * 16;
#pragma unroll
            for (int t = 0; t < 4; ++t) {
                int m = mbase + t * 8;
                float2 wn = *reinterpret_cast<const float2*>(&g_wnorm[m]);
                __half2 s0 = __floats2half2_rn(wn.x - 2.0f * acc[rt][t][0],
                                               wn.y - 2.0f * acc[rt][t][1]);
                __half2 s1 = __floats2half2_rn(wn.x - 2.0f * acc[rt][t][2],
                                               wn.y - 2.0f * acc[rt][t][3]);
                *reinterpret_cast<__half2*>(&g_scores[(size_t)br * MUNITS + m]) = s0;
                *reinterpret_cast<__half2*>(&g_scores[(size_t)(br + 8) * MUNITS + m]) = s1;
            }
        }
        __syncthreads();   // protect buf^1 before next issueW overwrite
    }
}

// ---------------- argmin + exact fp32 rescue + fused scatter ----------------
__global__ __launch_bounds__(256) void k_bmu(const float* __restrict__ X,
                                             const float* __restrict__ W,
                                             float* __restrict__ outloc) {
    __shared__ __align__(16) float xs[256];
    __shared__ float redv[256];
    __shared__ int   redi[256];
    __shared__ int   s_node;
    int b = blockIdx.x;
    int t = threadIdx.x;

    xs[t] = X[(size_t)b * DIM + t];

    // each thread owns 16 contiguous approx scores (fp16), kept as fp32 regs
    float v[16];
    const uint4* sp = reinterpret_cast<const uint4*>(g_scores + (size_t)b * MUNITS + t * 16);
    float amin = FLT_MAX;
#pragma unroll
    for (int i = 0; i < 2; ++i) {
        uint4 q = sp[i];
        const __half2* h = reinterpret_cast<const __half2*>(&q);
#pragma unroll
        for (int j = 0; j < 4; ++j) {
            float2 f = __half22float2(h[j]);
            v[i * 8 + j * 2 + 0] = f.x;
            v[i * 8 + j * 2 + 1] = f.y;
            amin = fminf(amin, fminf(f.x, f.y));
        }
    }
    redv[t] = amin;
    __syncthreads();
#pragma unroll
    for (int s = 128; s > 0; s >>= 1) {
        if (t < s) redv[t] = fminf(redv[t], redv[t + s]);
        __syncthreads();
    }
    float thr = redv[0] + MARGIN;
    __syncthreads();

    float bestv = FLT_MAX;
    int   besti = 0x7FFFFFFF;
#pragma unroll
    for (int i = 0; i < 16; ++i) {
        if (v[i] <= thr) {
            int m = t * 16 + i;
            const float4* wp = reinterpret_cast<const float4*>(W + (size_t)m * DIM);
            const float4* xp = reinterpret_cast<const float4*>(xs);
            float a0 = 0.f, a1 = 0.f, a2 = 0.f, a3 = 0.f;
#pragma unroll 8
            for (int d = 0; d < 64; ++d) {
                float4 wv = __ldg(wp + d);
                float4 xv = xp[d];
                a0 += xv.x * wv.x; a1 += xv.y * wv.y;
                a2 += xv.z * wv.z; a3 += xv.w * wv.w;
            }
            float ex = g_wnorm[m] - 2.0f * ((a0 + a1) + (a2 + a3));
            if (ex < bestv || (ex == bestv && m < besti)) { bestv = ex; besti = m; }
        }
    }
    redv[t] = bestv;
    redi[t] = besti;
    __syncthreads();
#pragma unroll
    for (int s = 128; s > 0; s >>= 1) {
        if (t < s) {
            float ov = redv[t + s]; int oi = redi[t + s];
            if (ov < redv[t] || (ov == redv[t] && oi < redi[t])) {
                redv[t] = ov; redi[t] = oi;
            }
        }
        __syncthreads();
    }
    if (t == 0) {
        int bi = redi[0];
        s_node = bi;
        if (outloc) {
            outloc[2 * b + 0] = (float)(bi >> 6);
            outloc[2 * b + 1] = (float)(bi & 63);
        }
        atomicAdd(&g_cnt[bi], 1.0f);
    }
    __syncthreads();
    // ---- fused scatter: S[node] += x_b ----
    atomicAdd(&g_S[(size_t)s_node * DIM + t], xs[t]);
}

// ---------------- row convolution (+ count convolution in blocks >=256) ----
__global__ void k_conv() {
    __shared__ float Ss[64][64];
    __shared__ float ts[64];
    int tid = threadIdx.x;
    if (blockIdx.x >= 256) {               // ---- count conv (16 blocks) ----
        int gid = (blockIdx.x - 256) * 256 + tid;   // rm*64 + cb
        int rm = gid >> 6, cb = gid & 63;
        float acc = 0.0f;
        for (int rb = 0; rb < 64; ++rb) {
            int di = rm - rb; di = di < 0 ? -di : di;
            acc += g_t[di] * g_cnt[rb * 64 + cb];
        }
        g_c1[gid] = acc;
        return;
    }
    int cb = blockIdx.x >> 2;
    int dbase = (blockIdx.x & 3) * 64;
    if (tid < 64) ts[tid] = g_t[tid];
#pragma unroll
    for (int i = 0; i < 16; ++i) {
        int idx = tid + i * 256;
        int rb = idx >> 6, dd = idx & 63;
        Ss[rb][dd] = g_S[(size_t)(rb * 64 + cb) * DIM + dbase + dd];
    }
    __syncthreads();
    int dd = tid & 63;
    int rm0 = (tid >> 6) * 16;
    float acc[16];
#pragma unroll
    for (int r = 0; r < 16; ++r) acc[r] = 0.0f;
    for (int rb = 0; rb < 64; ++rb) {
        float s = Ss[rb][dd];
#pragma unroll
        for (int r = 0; r < 16; ++r) {
            int di = rm0 + r - rb; di = di < 0 ? -di : di;
            acc[r] += ts[di] * s;
        }
    }
#pragma unroll
    for (int r = 0; r < 16; ++r)
        g_T1[(size_t)((rm0 + r) * 64 + cb) * DIM + dbase + dd] = acc[r];
}

// ---------------- column convolution + divide -> new weights ----------------
__global__ void k_finalize(float* __restrict__ outW) {
    __shared__ float T1s[64][64];
    __shared__ float ts[64];
    __shared__ float c1s[64];
    __shared__ float dens[64];
    int rm = blockIdx.x >> 2;
    int dbase = (blockIdx.x & 3) * 64;
    int tid = threadIdx.x;
    if (tid < 64) { ts[tid] = g_t[tid]; c1s[tid] = g_c1[rm * 64 + tid]; }
#pragma unroll
    for (int i = 0; i < 16; ++i) {
        int idx = tid + i * 256;
        int cb = idx >> 6, dd = idx & 63;
        T1s[cb][dd] = g_T1[(size_t)(rm * 64 + cb) * DIM + dbase + dd];
    }
    __syncthreads();
    float alpha = g_alpha;
    if (tid < 64) {
        int cm = tid;
        float acc = 0.0f;
        for (int cb = 0; cb < 64; ++cb) {
            int di = cm - cb; di = di < 0 ? -di : di;
            acc += ts[di] * c1s[cb];
        }
        dens[cm] = alpha * acc + 1e-12f;
    }
    __syncthreads();
    int dd = tid & 63;
    int cm0 = (tid >> 6) * 16;
    float acc[16];
#pragma unroll
    for (int c = 0; c < 16; ++c) acc[c] = 0.0f;
    for (int cb = 0; cb < 64; ++cb) {
        float s = T1s[cb][dd];
#pragma unroll
        for (int c = 0; c < 16; ++c) {
            int di = cm0 + c - cb; di = di < 0 ? -di : di;
            acc[c] += ts[di] * s;
        }
    }
#pragma unroll
    for (int c = 0; c < 16; ++c) {
        int cm = cm0 + c;
        outW[(size_t)(rm * 64 + cm) * DIM + dbase + dd] = alpha * acc[c] / dens[cm];
    }
}

// ---------------- launch ----------------
extern "C" void kernel_launch(void* const* d_in, const int* in_sizes, int n_in,
                              void* d_out, int out_size) {
    const float* X = (const float*)d_in[0];
    const float* W = (const float*)d_in[1];
    const int* epoch = (const int*)d_in[2];

    float* out = (float*)d_out;
    float* outB = nullptr;
    float* outW = nullptr;
    if (out_size >= BATCH * 2 + MUNITS * DIM) {
        outB = out;
        outW = out + (out_size - MUNITS * DIM);
    } else {
        outW = out;
    }

    static int smem_set = 0;
    if (!smem_set) {
        cudaFuncSetAttribute(k_scores, cudaFuncAttributeMaxDynamicSharedMemorySize,
                             KS_SMEM);
        smem_set = 1;
    }

    k_pre<<<3073, 256>>>(X, W, epoch);
    k_scores<<<dim3(MSPLIT, BATCH / 128), 256, KS_SMEM>>>();
    k_bmu<<<BATCH, 256>>>(X, W, outB);
    k_conv<<<272, 256>>>();
    k_finalize<<<256, 256>>>(outW);
}

// round 13
// speedup vs baseline: 3.2477x; 1.1256x over previous
#include <cuda_runtime.h>
#include <cuda_bf16.h>
#include <cuda_fp16.h>
#include <cstdint>
#include <stdint.h>
#include <math.h>
#include <float.h>

// ---------------- problem constants ----------------
#define BATCH 8192
#define DIM   256
#define MROWS 64
#define NCOLS 64
#define MUNITS (MROWS * NCOLS)   // 4096
#define MARGIN 6.0f              // bf16-GEMM + fp16-store rescue margin

// k_scores tiling: BT=128 batch rows, MSPLIT=2 -> 128 CTAs (one wave)
#define MSPLIT 2
#define MPER (MUNITS / MSPLIT)   // 2048 m per CTA
#define MCHUNKS (MPER / 64)      // 32 chunks of 64 m
#define SM_X 0                   // X tile: 128 x 256 bf16 = 65536 B
#define SM_W0 65536              // W triple buffer: 3 x 32768 B
#define SM_WBUF 32768
#define KS_SMEM (65536 + 3 * 32768)   // 163840

// ---------------- device scratch (no allocation allowed) ----------------
__device__ __half g_scores[(size_t)BATCH * MUNITS];  // approx scores (67MB)
__device__ __nv_bfloat16 g_Xb[BATCH * DIM];
__device__ __nv_bfloat16 g_Wb[MUNITS * DIM];
__device__ float g_S[MUNITS * DIM];    // per-node scatter sums
__device__ float g_T1[MUNITS * DIM];   // row-convolved sums
__device__ float g_cnt[MUNITS];        // per-node counts
__device__ float g_c1[MUNITS];         // row-convolved counts
__device__ float g_wnorm[MUNITS];      // ||w_m||^2
__device__ float g_t[64];              // t[d] = exp(-d^2/denom)
__device__ float g_alpha;

// ---------------- PTX helpers (all plain sm_80+ features) ----------------
__device__ __forceinline__ uint32_t s2u(const void* p) {
    uint32_t a;
    asm("{ .reg .u64 t; cvta.to.shared.u64 t, %1; cvt.u32.u64 %0, t; }"
        : "=r"(a) : "l"(p));
    return a;
}

#define LDSM_X4(r0, r1, r2, r3, addr) \
    asm volatile("ldmatrix.sync.aligned.m8n8.x4.shared.b16 {%0,%1,%2,%3}, [%4];" \
        : "=r"(r0), "=r"(r1), "=r"(r2), "=r"(r3) : "r"(addr))

#define MMA16816(d, a0, a1, a2, a3, b0, b1) \
    asm volatile("mma.sync.aligned.m16n8k16.row.col.f32.bf16.bf16.f32 " \
        "{%0,%1,%2,%3}, {%4,%5,%6,%7}, {%8,%9}, {%0,%1,%2,%3};" \
        : "+f"((d)[0]), "+f"((d)[1]), "+f"((d)[2]), "+f"((d)[3]) \
        : "r"(a0), "r"(a1), "r"(a2), "r"(a3), "r"(b0), "r"(b1))

#define CP_ASYNC16(saddr, gaddr) \
    asm volatile("cp.async.ca.shared.global [%0], [%1], 16;" \
        :: "r"(saddr), "l"(gaddr))

// ---------------- mega-prep: cvtX + cvtW + wnorm + zero + exp table -------
__global__ __launch_bounds__(256) void k_pre(const float* __restrict__ X,
                                             const float* __restrict__ W,
                                             const int* __restrict__ epoch_p) {
    __shared__ float sred[256];
    int blk = blockIdx.x;
    int tid = threadIdx.x;

    if (blk < 2048) {                      // ---- cvtX ----
        int i = blk * 256 + tid;
        float4 v = reinterpret_cast<const float4*>(X)[i];
        __nv_bfloat162* d = reinterpret_cast<__nv_bfloat162*>(g_Xb);
        d[2 * i]     = __floats2bfloat162_rn(v.x, v.y);
        d[2 * i + 1] = __floats2bfloat162_rn(v.z, v.w);
    } else if (blk < 3072) {               // ---- cvtW + wnorm + zero S ----
        int j = blk - 2048;                // 0..1023, covers W rows 4j..4j+3
        int i = j * 256 + tid;             // float4 index
        float4 v = reinterpret_cast<const float4*>(W)[i];
        __nv_bfloat162* d = reinterpret_cast<__nv_bfloat162*>(g_Wb);
        d[2 * i]     = __floats2bfloat162_rn(v.x, v.y);
        d[2 * i + 1] = __floats2bfloat162_rn(v.z, v.w);
        reinterpret_cast<float4*>(g_S)[i] = make_float4(0.f, 0.f, 0.f, 0.f);
        sred[tid] = v.x * v.x + v.y * v.y + v.z * v.z + v.w * v.w;
        __syncthreads();
#pragma unroll
        for (int s = 32; s > 0; s >>= 1) {
            if ((tid & 63) < s) sred[tid] += sred[tid + s];
            __syncthreads();
        }
        if ((tid & 63) == 0) g_wnorm[4 * j + (tid >> 6)] = sred[tid];
    } else {                               // ---- table + cnt zero ----
        if (tid < 64) {
            float ep = (float)(*epoch_p);
            float radius = 32.0f - ep * (31.0f / 99.0f);
            float hs = radius * 0.5f;
            float denom = 2.0f * hs * hs;
            g_t[tid] = expf(-((float)(tid * tid)) / denom);
            if (tid == 0) g_alpha = 0.1f * (1.0f - ep / 100.0f);
        }
#pragma unroll
        for (int k = 0; k < 16; ++k) g_cnt[tid + k * 256] = 0.0f;
    }
}

// ---------------- mma.sync score GEMM (3-stage cp.async pipeline) ---------
__global__ __launch_bounds__(256) void k_scores() {
    extern __shared__ char sm[];
    const int tid = threadIdx.x;
    const int lane = tid & 31;
    const int wid = tid >> 5;
    const int warp_b = wid >> 1;
    const int warp_m = wid & 1;
    const int bbase = blockIdx.y * 128;
    const int mstart = blockIdx.x * MPER;

    // ---- load X tile 128 x 256 bf16, swizzled ----
#pragma unroll
    for (int it = 0; it < 16; ++it) {
        int idx = tid + it * 256;       // uint4 index, 4096 total
        int row = idx >> 5;
        int c = idx & 31;
        uint4 v = reinterpret_cast<const uint4*>(g_Xb)[(size_t)(bbase + row) * 32 + c];
        *reinterpret_cast<uint4*>(sm + SM_X + row * 512 + ((c ^ (row & 7)) << 4)) = v;
    }

    auto issueW = [&](int chunk) {
        const char* gb = reinterpret_cast<const char*>(g_Wb)
                       + (size_t)(mstart + chunk * 64) * 512;
        char* sb = sm + SM_W0 + (chunk % 3) * SM_WBUF;
#pragma unroll
        for (int it = 0; it < 8; ++it) {
            int idx = tid + it * 256;
            int row = idx >> 5;
            int c = idx & 31;
            uint32_t saddr = s2u(sb + row * 512 + ((c ^ (row & 7)) << 4));
            CP_ASYNC16(saddr, gb + row * 512 + c * 16);
        }
        asm volatile("cp.async.commit_group;" ::: "memory");
    };
    issueW(0);
    issueW(1);

    // lane-derived ldmatrix bases
    const int l15 = lane & 15;
    const int hi = lane >> 4;
    const int s7 = l15 & 7;
    const uint32_t aBase0 = s2u(sm + SM_X + (warp_b * 32 + l15) * 512);
    const uint32_t aBase1 = s2u(sm + SM_X + (warp_b * 32 + 16 + l15) * 512);
    const int b0off = (warp_m * 32 + l15) * 512;
    const int b1off = (warp_m * 32 + 16 + l15) * 512;

    const int brow0 = bbase + warp_b * 32 + (lane >> 2);
    const int mcol0 = warp_m * 32 + (lane & 3) * 2;

    for (int ch = 0; ch < MCHUNKS; ++ch) {
        if (ch + 1 < MCHUNKS) {
            asm volatile("cp.async.wait_group 1;" ::: "memory");
        } else {
            asm volatile("cp.async.wait_group 0;" ::: "memory");
        }
        __syncthreads();   // chunk ch landed; prior readers of buf (ch+2)%3 done
        if (ch + 2 < MCHUNKS) issueW(ch + 2);

        const int buf = ch % 3;
        const uint32_t wBase0 = s2u(sm + SM_W0 + buf * SM_WBUF + b0off);
        const uint32_t wBase1 = s2u(sm + SM_W0 + buf * SM_WBUF + b1off);

        float acc[2][4][4];
#pragma unroll
        for (int rt = 0; rt < 2; ++rt)
#pragma unroll
            for (int i = 0; i < 4; ++i)
#pragma unroll
                for (int j = 0; j < 4; ++j) acc[rt][i][j] = 0.0f;

#pragma unroll
        for (int kk = 0; kk < 16; ++kk) {
            int off = (((kk * 2 + hi) ^ s7) << 4);
            uint32_t a0, a1, a2, a3, c0, c1, c2, c3;
            LDSM_X4(a0, a1, a2, a3, aBase0 + off);
            LDSM_X4(c0, c1, c2, c3, aBase1 + off);
            uint32_t p0, p1, p2, p3, q0, q1, q2, q3;
            LDSM_X4(p0, p1, p2, p3, wBase0 + off);
            LDSM_X4(q0, q1, q2, q3, wBase1 + off);
            MMA16816(acc[0][0], a0, a1, a2, a3, p0, p2);
            MMA16816(acc[0][1], a0, a1, a2, a3, p1, p3);
            MMA16816(acc[0][2], a0, a1, a2, a3, q0, q2);
            MMA16816(acc[0][3], a0, a1, a2, a3, q1, q3);
            MMA16816(acc[1][0], c0, c1, c2, c3, p0, p2);
            MMA16816(acc[1][1], c0, c1, c2, c3, p1, p3);
            MMA16816(acc[1][2], c0, c1, c2, c3, q0, q2);
            MMA16816(acc[1][3], c0, c1, c2, c3, q1, q3);
        }

        // ---- epilogue: score = wnorm - 2*dot, write half2 pairs ----
        int mbase = mstart + ch * 64 + mcol0;
#pragma unroll
        for (int rt = 0; rt < 2; ++rt) {
            int br = brow0 + rt * 16;
#pragma unroll
            for (int t = 0; t < 4; ++t) {
                int m = mbase + t * 8;
                float2 wn = *reinterpret_cast<const float2*>(&g_wnorm[m]);
                __half2 s0 = __floats2half2_rn(wn.x - 2.0f * acc[rt][t][0],
                                               wn.y - 2.0f * acc[rt][t][1]);
                __half2 s1 = __floats2half2_rn(wn.x - 2.0f * acc[rt][t][2],
                                               wn.y - 2.0f * acc[rt][t][3]);
                *reinterpret_cast<__half2*>(&g_scores[(size_t)br * MUNITS + m]) = s0;
                *reinterpret_cast<__half2*>(&g_scores[(size_t)(br + 8) * MUNITS + m]) = s1;
            }
        }
    }
}

// ---------------- argmin + exact fp32 rescue + fused scatter ----------------
__global__ __launch_bounds__(256) void k_bmu(const float* __restrict__ X,
                                             const float* __restrict__ W,
                                             float* __restrict__ outloc) {
    __shared__ __align__(16) float xs[256];
    __shared__ float wmin[8];
    __shared__ float wv2[8];
    __shared__ int   wi2[8];
    __shared__ int   s_node;
    int b = blockIdx.x;
    int t = threadIdx.x;
    int lane = t & 31;
    int wid = t >> 5;

    xs[t] = X[(size_t)b * DIM + t];

    // 16 fp16 scores per thread, kept packed; hardware half2 min scan
    uint4 q0 = reinterpret_cast<const uint4*>(g_scores + (size_t)b * MUNITS + t * 16)[0];
    uint4 q1 = reinterpret_cast<const uint4*>(g_scores + (size_t)b * MUNITS + t * 16)[1];
    const __half2* h0 = reinterpret_cast<const __half2*>(&q0);
    const __half2* h1 = reinterpret_cast<const __half2*>(&q1);
    __half2 hm = __hmin2(__hmin2(h0[0], h0[1]), __hmin2(h0[2], h0[3]));
    hm = __hmin2(hm, __hmin2(__hmin2(h1[0], h1[1]), __hmin2(h1[2], h1[3])));
    float amin = fminf(__low2float(hm), __high2float(hm));
    // warp-shuffle min
#pragma unroll
    for (int o = 16; o > 0; o >>= 1)
        amin = fminf(amin, __shfl_down_sync(0xFFFFFFFFu, amin, o));
    if (lane == 0) wmin[wid] = amin;
    __syncthreads();
    float thr = wmin[0];
#pragma unroll
    for (int w = 1; w < 8; ++w) thr = fminf(thr, wmin[w]);
    thr += MARGIN;

    float bestv = FLT_MAX;
    int   besti = 0x7FFFFFFF;
#pragma unroll
    for (int i = 0; i < 16; ++i) {
        float sv;
        if (i < 8) {
            __half2 hp = h0[i >> 1];
            sv = (i & 1) ? __high2float(hp) : __low2float(hp);
        } else {
            __half2 hp = h1[(i - 8) >> 1];
            sv = (i & 1) ? __high2float(hp) : __low2float(hp);
        }
        if (sv <= thr) {
            int m = t * 16 + i;
            const float4* wp = reinterpret_cast<const float4*>(W + (size_t)m * DIM);
            const float4* xp = reinterpret_cast<const float4*>(xs);
            float a0 = 0.f, a1 = 0.f, a2 = 0.f, a3 = 0.f;
#pragma unroll 8
            for (int d = 0; d < 64; ++d) {
                float4 wv = __ldg(wp + d);
                float4 xv = xp[d];
                a0 += xv.x * wv.x; a1 += xv.y * wv.y;
                a2 += xv.z * wv.z; a3 += xv.w * wv.w;
            }
            float ex = g_wnorm[m] - 2.0f * ((a0 + a1) + (a2 + a3));
            if (ex < bestv || (ex == bestv && m < besti)) { bestv = ex; besti = m; }
        }
    }
    // warp-shuffle argmin (value, index) with lowest-index tie-break
#pragma unroll
    for (int o = 16; o > 0; o >>= 1) {
        float ov = __shfl_down_sync(0xFFFFFFFFu, bestv, o);
        int   oi = __shfl_down_sync(0xFFFFFFFFu, besti, o);
        if (ov < bestv || (ov == bestv && oi < besti)) { bestv = ov; besti = oi; }
    }
    if (lane == 0) { wv2[wid] = bestv; wi2[wid] = besti; }
    __syncthreads();
    if (t == 0) {
        float bv = wv2[0]; int bi = wi2[0];
#pragma unroll
        for (int w = 1; w < 8; ++w) {
            if (wv2[w] < bv || (wv2[w] == bv && wi2[w] < bi)) { bv = wv2[w]; bi = wi2[w]; }
        }
        s_node = bi;
        if (outloc) {
            outloc[2 * b + 0] = (float)(bi >> 6);
            outloc[2 * b + 1] = (float)(bi & 63);
        }
        atomicAdd(&g_cnt[bi], 1.0f);
    }
    __syncthreads();
    atomicAdd(&g_S[(size_t)s_node * DIM + t], xs[t]);
}

// ---------------- row convolution (+ count convolution in blocks >=256) ----
// shifted table: tsh[x+63] = t[|x|], removes abs from the inner loop
__global__ void k_conv() {
    __shared__ float Ss[64][64];
    __shared__ float tsh[128];
    int tid = threadIdx.x;
    if (blockIdx.x >= 256) {               // ---- count conv (16 blocks) ----
        if (tid < 127) tsh[tid] = g_t[tid < 63 ? 63 - tid : tid - 63];
        __syncthreads();
        int gid = (blockIdx.x - 256) * 256 + tid;   // rm*64 + cb
        int rm = gid >> 6, cb = gid & 63;
        float acc = 0.0f;
        for (int rb = 0; rb < 64; ++rb)
            acc += tsh[rm + 63 - rb] * g_cnt[rb * 64 + cb];
        g_c1[gid] = acc;
        return;
    }
    int cb = blockIdx.x >> 2;
    int dbase = (blockIdx.x & 3) * 64;
    if (tid < 127) tsh[tid] = g_t[tid < 63 ? 63 - tid : tid - 63];
#pragma unroll
    for (int i = 0; i < 16; ++i) {
        int idx = tid + i * 256;
        int rb = idx >> 6, dd = idx & 63;
        Ss[rb][dd] = g_S[(size_t)(rb * 64 + cb) * DIM + dbase + dd];
    }
    __syncthreads();
    int dd = tid & 63;
    int rm0 = (tid >> 6) * 16;
    float acc[16];
#pragma unroll
    for (int r = 0; r < 16; ++r) acc[r] = 0.0f;
    for (int rb = 0; rb < 64; ++rb) {
        float s = Ss[rb][dd];
        const float* tb = &tsh[rm0 + 63 - rb];
#pragma unroll
        for (int r = 0; r < 16; ++r) acc[r] += tb[r] * s;
    }
#pragma unroll
    for (int r = 0; r < 16; ++r)
        g_T1[(size_t)((rm0 + r) * 64 + cb) * DIM + dbase + dd] = acc[r];
}

// ---------------- column convolution + divide -> new weights ----------------
__global__ void k_finalize(float* __restrict__ outW) {
    __shared__ float T1s[64][64];
    __shared__ float tsh[128];
    __shared__ float c1s[64];
    __shared__ float dens[64];
    int rm = blockIdx.x >> 2;
    int dbase = (blockIdx.x & 3) * 64;
    int tid = threadIdx.x;
    if (tid < 127) tsh[tid] = g_t[tid < 63 ? 63 - tid : tid - 63];
    if (tid >= 128 && tid < 192) c1s[tid - 128] = g_c1[rm * 64 + (tid - 128)];
#pragma unroll
    for (int i = 0; i < 16; ++i) {
        int idx = tid + i * 256;
        int cb = idx >> 6, dd = idx & 63;
        T1s[cb][dd] = g_T1[(size_t)(rm * 64 + cb) * DIM + dbase + dd];
    }
    __syncthreads();
    float alpha = g_alpha;
    if (tid < 64) {
        int cm = tid;
        float acc = 0.0f;
        for (int cb = 0; cb < 64; ++cb)
            acc += tsh[cm + 63 - cb] * c1s[cb];
        dens[cm] = alpha * acc + 1e-12f;
    }
    __syncthreads();
    int dd = tid & 63;
    int cm0 = (tid >> 6) * 16;
    float acc[16];
#pragma unroll
    for (int c = 0; c < 16; ++c) acc[c] = 0.0f;
    for (int cb = 0; cb < 64; ++cb) {
        float s = T1s[cb][dd];
        const float* tb = &tsh[cm0 + 63 - cb];
#pragma unroll
        for (int c = 0; c < 16; ++c) acc[c] += tb[c] * s;
    }
#pragma unroll
    for (int c = 0; c < 16; ++c) {
        int cm = cm0 + c;
        outW[(size_t)(rm * 64 + cm) * DIM + dbase + dd] = alpha * acc[c] / dens[cm];
    }
}

// ---------------- launch ----------------
extern "C" void kernel_launch(void* const* d_in, const int* in_sizes, int n_in,
                              void* d_out, int out_size) {
    const float* X = (const float*)d_in[0];
    const float* W = (const float*)d_in[1];
    const int* epoch = (const int*)d_in[2];

    float* out = (float*)d_out;
    float* outB = nullptr;
    float* outW = nullptr;
    if (out_size >= BATCH * 2 + MUNITS * DIM) {
        outB = out;
        outW = out + (out_size - MUNITS * DIM);
    } else {
        outW = out;
    }

    static int smem_set = 0;
    if (!smem_set) {
        cudaFuncSetAttribute(k_scores, cudaFuncAttributeMaxDynamicSharedMemorySize,
                             KS_SMEM);
        smem_set = 1;
    }

    k_pre<<<3073, 256>>>(X, W, epoch);
    k_scores<<<dim3(MSPLIT, BATCH / 128), 256, KS_SMEM>>>();
    k_bmu<<<BATCH, 256>>>(X, W, outB);
    k_conv<<<272, 256>>>();
    k_finalize<<<256, 256>>>(outW);
}